// round 1
// baseline (speedup 1.0000x reference)
#include <cuda_runtime.h>

// QINCo: D=128, M=8 (1 + 7 neural steps), K=256 codes, L=2 MLP layers, H=256, BS=1024
namespace {
constexpr int D_  = 128;
constexpr int K_  = 256;
constexpr int M_  = 8;
constexpr int H_  = 256;
constexpr int BS_ = 1024;
constexpr int NR  = BS_ * K_;          // 262144 candidate rows per step

constexpr int OUT_CODES = BS_ * D_;            // 131072
constexpr int OUT_SIDE  = OUT_CODES + BS_ * M_; // 139264
constexpr int SIDE_SZ   = BS_ * D_;            // 131072 per side tensor
}

// ---- scratch (device globals: allocation-free) ----
__device__ __align__(128) float g_z[NR * D_];          // candidate vectors  (134 MB)
__device__ __align__(128) float g_h[NR * H_];          // MLP hidden         (268 MB)
__device__ __align__(128) float g_cbz[(M_-1) * K_ * D_]; // cb + cb@Wz^T + bc
__device__ __align__(128) float g_y[BS_ * D_];         // xhat @ Wx^T
__device__ __align__(128) float g_xa[BS_ * D_];        // xhat ping
__device__ __align__(128) float g_xb[BS_ * D_];        // xhat pong

__device__ __forceinline__ void warp_red2(float& a, float& b) {
#pragma unroll
    for (int o = 16; o; o >>= 1) {
        a += __shfl_xor_sync(0xffffffffu, a, o);
        b += __shfl_xor_sync(0xffffffffu, b, o);
    }
}

// ---- cbz[m][k][:] = cb + cb @ Wz^T + bc  (Wz = Wc[m][:, :D]) ----
__global__ void k_cbz(const float* __restrict__ cbs, const float* __restrict__ Wc,
                      const float* __restrict__ bc) {
    int r = blockIdx.x;            // 0..7*256-1
    int m = r >> 8, k = r & 255;
    __shared__ float cb[D_];
    int d = threadIdx.x;
    cb[d] = cbs[(m * K_ + k) * D_ + d];
    __syncthreads();
    const float* wrow = Wc + (m * D_ + d) * (2 * D_);   // Wz part: cols [0,128)
    float acc = cb[d] + bc[m * D_ + d];
#pragma unroll 8
    for (int j = 0; j < D_; ++j) acc = fmaf(cb[j], wrow[j], acc);
    g_cbz[r * D_ + d] = acc;
}

// ---- y[b][:] = xhat @ Wx^T  (Wx = Wc[m][:, D:2D]) ----
__global__ void k_y(const float* __restrict__ Wc, int m, int ping) {
    const float* xin = ping ? g_xb : g_xa;
    int b = blockIdx.x, d = threadIdx.x;
    __shared__ float xh[D_];
    xh[d] = xin[b * D_ + d];
    __syncthreads();
    const float* wrow = Wc + (m * D_ + d) * (2 * D_) + D_;
    float acc = 0.f;
#pragma unroll 8
    for (int j = 0; j < D_; ++j) acc = fmaf(xh[j], wrow[j], acc);
    g_y[b * D_ + d] = acc;
}

// ---- z[b][k][:] = cbz[m][k][:] + y[b][:] ----
__global__ void k_buildz(int m) {
    int i = blockIdx.x * blockDim.x + threadIdx.x;   // float4 index, NR*32 total
    int d4 = i & 31;
    int k  = (i >> 5) & 255;
    int b  = i >> 13;
    const float4* c4 = (const float4*)(g_cbz + m * K_ * D_);
    float4 a = c4[k * 32 + d4];
    float4 y = ((const float4*)g_y)[b * 32 + d4];
    a.x += y.x; a.y += y.y; a.z += y.z; a.w += y.w;
    ((float4*)g_z)[i] = a;
}

// ---- SGEMM: C[NR,O] (+)= (relu?)(A[NR,K] * W[O,K]^T), 128x128 tiles, 8x8 microtile ----
template <bool RELU, bool ACC, int K, int O>
__device__ __forceinline__ void gemm_body(const float* __restrict__ A,
                                          const float* __restrict__ W,
                                          float* __restrict__ C) {
    __shared__ float As[8][128];
    __shared__ float Bs[8][128];
    const int tid  = threadIdx.x;
    const int cRow = blockIdx.y * 128;
    const int cCol = blockIdx.x * 128;
    const int tRow = (tid >> 4) * 8;
    const int tCol = (tid & 15) * 8;
    const int rA = tid >> 1;
    const int cA = (tid & 1) * 4;

    float acc[8][8] = {};
    const float* Ap = A + (cRow + rA) * K + cA;
    const float* Wp = W + (cCol + rA) * K + cA;

    for (int k0 = 0; k0 < K; k0 += 8) {
        float4 a4 = *(const float4*)(Ap + k0);
        float4 b4 = *(const float4*)(Wp + k0);
        As[cA + 0][rA] = a4.x; As[cA + 1][rA] = a4.y;
        As[cA + 2][rA] = a4.z; As[cA + 3][rA] = a4.w;
        Bs[cA + 0][rA] = b4.x; Bs[cA + 1][rA] = b4.y;
        Bs[cA + 2][rA] = b4.z; Bs[cA + 3][rA] = b4.w;
        __syncthreads();
#pragma unroll
        for (int kk = 0; kk < 8; ++kk) {
            float rm[8], rn[8];
            *(float4*)(rm)     = *(const float4*)&As[kk][tRow];
            *(float4*)(rm + 4) = *(const float4*)&As[kk][tRow + 4];
            *(float4*)(rn)     = *(const float4*)&Bs[kk][tCol];
            *(float4*)(rn + 4) = *(const float4*)&Bs[kk][tCol + 4];
#pragma unroll
            for (int i = 0; i < 8; ++i)
#pragma unroll
                for (int j = 0; j < 8; ++j)
                    acc[i][j] = fmaf(rm[i], rn[j], acc[i][j]);
        }
        __syncthreads();
    }

#pragma unroll
    for (int i = 0; i < 8; ++i) {
        float* cp = C + (cRow + tRow + i) * O + cCol + tCol;
#pragma unroll
        for (int j4 = 0; j4 < 8; j4 += 4) {
            float4 v = make_float4(acc[i][j4], acc[i][j4 + 1], acc[i][j4 + 2], acc[i][j4 + 3]);
            if (ACC) {
                float4 o = *(const float4*)(cp + j4);
                v.x += o.x; v.y += o.y; v.z += o.z; v.w += o.w;
            }
            if (RELU) {
                v.x = fmaxf(v.x, 0.f); v.y = fmaxf(v.y, 0.f);
                v.z = fmaxf(v.z, 0.f); v.w = fmaxf(v.w, 0.f);
            }
            *(float4*)(cp + j4) = v;
        }
    }
}

__global__ void __launch_bounds__(256) k_gemm1(const float* __restrict__ W1) {
    gemm_body<true, false, D_, H_>(g_z, W1, g_h);      // h = relu(z @ W1^T)
}
__global__ void __launch_bounds__(256) k_gemm2(const float* __restrict__ W2) {
    gemm_body<false, true, H_, D_>(g_h, W2, g_z);      // z += h @ W2^T
}

// ---- step 0: argmin_k |x - cb0[k]|^2; write xhat, side0, code0 ----
__global__ void k_step0(const float* __restrict__ x, const float* __restrict__ cb0,
                        float* __restrict__ out) {
    int b = blockIdx.x, t = threadIdx.x;
    int w = t >> 5, lane = t & 31;
    __shared__ float4 xs[32];
    __shared__ float  sd[256];
    __shared__ int    si[256];
    if (t < 32) xs[t] = ((const float4*)x)[b * 32 + t];
    __syncthreads();
    float4 xv = xs[lane];
    for (int i = 0; i < 32; ++i) {
        int k = w * 32 + i;
        float4 c = ((const float4*)cb0)[k * 32 + lane];
        float a1 = c.x * c.x + c.y * c.y + c.z * c.z + c.w * c.w;
        float a2 = xv.x * c.x + xv.y * c.y + xv.z * c.z + xv.w * c.w;
        warp_red2(a1, a2);
        if (lane == 0) sd[k] = a1 - 2.f * a2;
    }
    si[t] = t;
    __syncthreads();
    for (int s = 128; s; s >>= 1) {
        if (t < s) {
            float o = sd[t + s]; int oi = si[t + s];
            if (o < sd[t] || (o == sd[t] && oi < si[t])) { sd[t] = o; si[t] = oi; }
        }
        __syncthreads();
    }
    int kb = si[0];
    if (t < D_) {
        float v = cb0[kb * D_ + t];
        g_xa[b * D_ + t] = v;
        out[OUT_SIDE + b * D_ + t] = v;       // side[0]
    }
    if (t == 0) out[OUT_CODES + b * M_] = (float)kb;
}

// ---- step m: zf = z + xhat; argmin_k (|zf|^2 - 2 x.zf); update xhat; emit outputs ----
__global__ void k_argupd(const float* __restrict__ x, float* __restrict__ out,
                         int m, int ping) {
    const float* xin = ping ? g_xb : g_xa;
    float*       xout = ping ? g_xa : g_xb;
    int b = blockIdx.x, t = threadIdx.x;
    int w = t >> 5, lane = t & 31;
    __shared__ float4 xs[32], hs[32];
    __shared__ float  sd[256];
    __shared__ int    si[256];
    if (t < 32) {
        xs[t] = ((const float4*)x)[b * 32 + t];
        hs[t] = ((const float4*)xin)[b * 32 + t];
    }
    __syncthreads();
    float4 xv = xs[lane], hv = hs[lane];
    const float4* zr = (const float4*)g_z + b * (K_ * 32);
    for (int i = 0; i < 32; ++i) {
        int k = w * 32 + i;
        float4 z = zr[k * 32 + lane];
        z.x += hv.x; z.y += hv.y; z.z += hv.z; z.w += hv.w;
        float a1 = z.x * z.x + z.y * z.y + z.z * z.z + z.w * z.w;
        float a2 = xv.x * z.x + xv.y * z.y + xv.z * z.z + xv.w * z.w;
        warp_red2(a1, a2);
        if (lane == 0) sd[k] = a1 - 2.f * a2;
    }
    si[t] = t;
    __syncthreads();
    for (int s = 128; s; s >>= 1) {
        if (t < s) {
            float o = sd[t + s]; int oi = si[t + s];
            if (o < sd[t] || (o == sd[t] && oi < si[t])) { sd[t] = o; si[t] = oi; }
        }
        __syncthreads();
    }
    int kb = si[0];
    if (t < D_) {
        float v = g_z[(b * K_ + kb) * D_ + t] + xin[b * D_ + t];
        xout[b * D_ + t] = v;
        out[OUT_SIDE + (m + 1) * SIDE_SZ + b * D_ + t] = v;  // side[m+1]
        if (m == M_ - 2) out[b * D_ + t] = v;                // final xhat
    }
    if (t == 0) out[OUT_CODES + b * M_ + m + 1] = (float)kb;
}

extern "C" void kernel_launch(void* const* d_in, const int* in_sizes, int n_in,
                              void* d_out, int out_size) {
    const float* x   = (const float*)d_in[0];
    const float* cb0 = (const float*)d_in[1];
    const float* cbs = (const float*)d_in[2];
    const float* Wc  = (const float*)d_in[3];
    const float* bc  = (const float*)d_in[4];
    const float* W1  = (const float*)d_in[5];
    const float* W2  = (const float*)d_in[6];
    float* out = (float*)d_out;

    k_cbz<<<(M_ - 1) * K_, D_>>>(cbs, Wc, bc);
    k_step0<<<BS_, 256>>>(x, cb0, out);

    int ping = 0;   // xhat currently in g_xa
    for (int m = 0; m < M_ - 1; ++m) {
        k_y<<<BS_, D_>>>(Wc, m, ping);
        k_buildz<<<(NR * 32) / 256, 256>>>(m);
        for (int l = 0; l < 2; ++l) {
            k_gemm1<<<dim3(H_ / 128, NR / 128), 256>>>(W1 + (m * 2 + l) * H_ * D_);
            k_gemm2<<<dim3(D_ / 128, NR / 128), 256>>>(W2 + (m * 2 + l) * D_ * H_);
        }
        k_argupd<<<BS_, 256>>>(x, out, m, ping);
        ping ^= 1;
    }
}

// round 2
// speedup vs baseline: 1.2720x; 1.2720x over previous
#include <cuda_runtime.h>

// QINCo: D=128, M=8 (1 + 7 neural steps), K=256 codes, L=2 MLP layers, H=256, BS=1024
namespace {
constexpr int D_  = 128;
constexpr int K_  = 256;
constexpr int M_  = 8;
constexpr int H_  = 256;
constexpr int BS_ = 1024;
constexpr int NR  = BS_ * K_;          // 262144 candidate rows per step

constexpr int OUT_CODES = BS_ * D_;             // 131072
constexpr int OUT_SIDE  = OUT_CODES + BS_ * M_; // 139264
constexpr int SIDE_SZ   = BS_ * D_;             // per side tensor
}

// ---- scratch (device globals: allocation-free) ----
__device__ __align__(128) float g_z[NR * D_];            // candidate vectors
__device__ __align__(128) float g_h[NR * H_];            // MLP hidden (layer 1 only)
__device__ __align__(128) float g_cbz[(M_-1) * K_ * D_]; // cb + cb@Wz^T + bc
__device__ __align__(128) float g_P1[(M_-1) * K_ * H_];  // cbz @ W1_0^T  (weight-only)
__device__ __align__(128) float g_y[BS_ * D_];           // xhat @ Wx^T
__device__ __align__(128) float g_Q1[BS_ * H_];          // y @ W1_0^T
__device__ __align__(128) float g_xa[BS_ * D_];          // xhat ping
__device__ __align__(128) float g_xb[BS_ * D_];          // xhat pong

__device__ __forceinline__ void warp_red2(float& a, float& b) {
#pragma unroll
    for (int o = 16; o; o >>= 1) {
        a += __shfl_xor_sync(0xffffffffu, a, o);
        b += __shfl_xor_sync(0xffffffffu, b, o);
    }
}

// ---- cbz[m][k][:] = cb + cb @ Wz^T + bc  (Wz = Wc[m][:, :D]) ----
__global__ void k_cbz(const float* __restrict__ cbs, const float* __restrict__ Wc,
                      const float* __restrict__ bc) {
    int r = blockIdx.x;            // 0..7*256-1
    int m = r >> 8, k = r & 255;
    __shared__ float cb[D_];
    int d = threadIdx.x;
    cb[d] = cbs[(m * K_ + k) * D_ + d];
    __syncthreads();
    const float* wrow = Wc + (m * D_ + d) * (2 * D_);   // Wz part: cols [0,128)
    float acc = cb[d] + bc[m * D_ + d];
#pragma unroll 8
    for (int j = 0; j < D_; ++j) acc = fmaf(cb[j], wrow[j], acc);
    g_cbz[r * D_ + d] = acc;
}

// ---- P1[m][k][h] = cbz[m][k] @ W1[m][0]^T  (weight-only precompute) ----
__global__ void k_p1(const float* __restrict__ W1) {
    int r = blockIdx.x;            // (m,k)
    int m = r >> 8;
    __shared__ float cb[D_];
    int h = threadIdx.x;           // 256 threads
    if (h < D_) cb[h] = g_cbz[r * D_ + h];
    __syncthreads();
    const float* wrow = W1 + (m * 2) * H_ * D_ + h * D_;   // W1[m][0][h][:]
    float acc = 0.f;
#pragma unroll 8
    for (int j = 0; j < D_; ++j) acc = fmaf(cb[j], wrow[j], acc);
    g_P1[r * H_ + h] = acc;
}

// ---- y[b][:] = xhat @ Wx^T  (Wx = Wc[m][:, D:2D]) ----
__global__ void k_y(const float* __restrict__ Wc, int m, int ping) {
    const float* xin = ping ? g_xb : g_xa;
    int b = blockIdx.x, d = threadIdx.x;
    __shared__ float xh[D_];
    xh[d] = xin[b * D_ + d];
    __syncthreads();
    const float* wrow = Wc + (m * D_ + d) * (2 * D_) + D_;
    float acc = 0.f;
#pragma unroll 8
    for (int j = 0; j < D_; ++j) acc = fmaf(xh[j], wrow[j], acc);
    g_y[b * D_ + d] = acc;
}

// ---- Q1[b][h] = y[b] @ W1[m][0]^T ----
__global__ void k_q1(const float* __restrict__ W1, int m) {
    int b = blockIdx.x, h = threadIdx.x;   // 256 threads
    __shared__ float ys[D_];
    if (h < D_) ys[h] = g_y[b * D_ + h];
    __syncthreads();
    const float* wrow = W1 + (m * 2) * H_ * D_ + h * D_;
    float acc = 0.f;
#pragma unroll 8
    for (int j = 0; j < D_; ++j) acc = fmaf(ys[j], wrow[j], acc);
    g_Q1[b * H_ + h] = acc;
}

// ============ double-buffered SGEMM core (128x128 tile, 8x8 microtile) ============
template <bool RELU, bool ACC, int K, int O>
__device__ __forceinline__ void gemm_std(const float* __restrict__ A,
                                         const float* __restrict__ W,
                                         float* __restrict__ C) {
    __shared__ float As[2][8][128];
    __shared__ float Bs[2][8][128];
    const int tid  = threadIdx.x;
    const int cRow = blockIdx.y * 128;
    const int cCol = blockIdx.x * 128;
    const int tRow = (tid >> 4) * 8;
    const int tCol = (tid & 15) * 8;
    const int rA = tid >> 1;
    const int cA = (tid & 1) * 4;

    float acc[8][8] = {};
    const float* Ap = A + (cRow + rA) * K + cA;
    const float* Wp = W + (cCol + rA) * K + cA;

    float4 a4 = *(const float4*)Ap;
    float4 b4 = *(const float4*)Wp;
    As[0][cA + 0][rA] = a4.x; As[0][cA + 1][rA] = a4.y;
    As[0][cA + 2][rA] = a4.z; As[0][cA + 3][rA] = a4.w;
    Bs[0][cA + 0][rA] = b4.x; Bs[0][cA + 1][rA] = b4.y;
    Bs[0][cA + 2][rA] = b4.z; Bs[0][cA + 3][rA] = b4.w;
    __syncthreads();

    constexpr int NT = K / 8;
    int buf = 0;
#pragma unroll 1
    for (int it = 0; it < NT; ++it) {
        float4 an, bn;
        if (it + 1 < NT) {
            an = *(const float4*)(Ap + (it + 1) * 8);
            bn = *(const float4*)(Wp + (it + 1) * 8);
        }
#pragma unroll
        for (int kk = 0; kk < 8; ++kk) {
            float rm[8], rn[8];
            *(float4*)(rm)     = *(const float4*)&As[buf][kk][tRow];
            *(float4*)(rm + 4) = *(const float4*)&As[buf][kk][tRow + 4];
            *(float4*)(rn)     = *(const float4*)&Bs[buf][kk][tCol];
            *(float4*)(rn + 4) = *(const float4*)&Bs[buf][kk][tCol + 4];
#pragma unroll
            for (int i = 0; i < 8; ++i)
#pragma unroll
                for (int j = 0; j < 8; ++j)
                    acc[i][j] = fmaf(rm[i], rn[j], acc[i][j]);
        }
        if (it + 1 < NT) {
            int nb = buf ^ 1;
            As[nb][cA + 0][rA] = an.x; As[nb][cA + 1][rA] = an.y;
            As[nb][cA + 2][rA] = an.z; As[nb][cA + 3][rA] = an.w;
            Bs[nb][cA + 0][rA] = bn.x; Bs[nb][cA + 1][rA] = bn.y;
            Bs[nb][cA + 2][rA] = bn.z; Bs[nb][cA + 3][rA] = bn.w;
            __syncthreads();
            buf = nb;
        }
    }

#pragma unroll
    for (int i = 0; i < 8; ++i) {
        float* cp = C + (cRow + tRow + i) * O + cCol + tCol;
#pragma unroll
        for (int j4 = 0; j4 < 8; j4 += 4) {
            float4 v = make_float4(acc[i][j4], acc[i][j4 + 1], acc[i][j4 + 2], acc[i][j4 + 3]);
            if (ACC) {
                float4 o = *(const float4*)(cp + j4);
                v.x += o.x; v.y += o.y; v.z += o.z; v.w += o.w;
            }
            if (RELU) {
                v.x = fmaxf(v.x, 0.f); v.y = fmaxf(v.y, 0.f);
                v.z = fmaxf(v.z, 0.f); v.w = fmaxf(v.w, 0.f);
            }
            *(float4*)(cp + j4) = v;
        }
    }
}

__global__ void __launch_bounds__(256) k_gemm1(const float* __restrict__ W1) {
    gemm_std<true, false, D_, H_>(g_z, W1, g_h);      // h = relu(z @ W1^T)  (layer 1)
}
__global__ void __launch_bounds__(256) k_gemm2(const float* __restrict__ W2) {
    gemm_std<false, true, H_, D_>(g_h, W2, g_z);      // z += h @ W2^T       (layer 1)
}

// ---- fused layer-0 GEMM2: z1[(b,k),d] = (cbz[k]+y[b]) + relu(P1[k]+Q1[b]) @ W2_0^T ----
// A operand (h0) is generated on the fly from L2-resident P1/Q1; base folded in epilogue.
__global__ void __launch_bounds__(256) k_gemm2_l0(const float* __restrict__ W2, int m) {
    constexpr int K = H_;   // 256
    constexpr int O = D_;   // 128
    __shared__ float As[2][8][128];
    __shared__ float Bs[2][8][128];
    const int tid  = threadIdx.x;
    const int cRow = blockIdx.y * 128;       // cCol = 0 (O=128, grid.x=1)
    const int tRow = (tid >> 4) * 8;
    const int tCol = (tid & 15) * 8;
    const int rA = tid >> 1;
    const int cA = (tid & 1) * 4;

    const int rGlob = cRow + rA;
    const int bb = rGlob >> 8;               // batch index of loaded row
    const int kk_ = rGlob & 255;             // code index of loaded row
    const float* Pp = g_P1 + (m * K_ + kk_) * H_ + cA;
    const float* Qp = g_Q1 + bb * H_ + cA;
    const float* Wp = W2 + rA * K + cA;

    float acc[8][8] = {};

    float4 p = *(const float4*)Pp;
    float4 q = *(const float4*)Qp;
    float4 b4 = *(const float4*)Wp;
    float4 a4 = make_float4(fmaxf(p.x + q.x, 0.f), fmaxf(p.y + q.y, 0.f),
                            fmaxf(p.z + q.z, 0.f), fmaxf(p.w + q.w, 0.f));
    As[0][cA + 0][rA] = a4.x; As[0][cA + 1][rA] = a4.y;
    As[0][cA + 2][rA] = a4.z; As[0][cA + 3][rA] = a4.w;
    Bs[0][cA + 0][rA] = b4.x; Bs[0][cA + 1][rA] = b4.y;
    Bs[0][cA + 2][rA] = b4.z; Bs[0][cA + 3][rA] = b4.w;
    __syncthreads();

    constexpr int NT = K / 8;   // 32
    int buf = 0;
#pragma unroll 1
    for (int it = 0; it < NT; ++it) {
        float4 an, bn;
        if (it + 1 < NT) {
            float4 pn = *(const float4*)(Pp + (it + 1) * 8);
            float4 qn = *(const float4*)(Qp + (it + 1) * 8);
            an = make_float4(fmaxf(pn.x + qn.x, 0.f), fmaxf(pn.y + qn.y, 0.f),
                             fmaxf(pn.z + qn.z, 0.f), fmaxf(pn.w + qn.w, 0.f));
            bn = *(const float4*)(Wp + (it + 1) * 8);
        }
#pragma unroll
        for (int kk = 0; kk < 8; ++kk) {
            float rm[8], rn[8];
            *(float4*)(rm)     = *(const float4*)&As[buf][kk][tRow];
            *(float4*)(rm + 4) = *(const float4*)&As[buf][kk][tRow + 4];
            *(float4*)(rn)     = *(const float4*)&Bs[buf][kk][tCol];
            *(float4*)(rn + 4) = *(const float4*)&Bs[buf][kk][tCol + 4];
#pragma unroll
            for (int i = 0; i < 8; ++i)
#pragma unroll
                for (int j = 0; j < 8; ++j)
                    acc[i][j] = fmaf(rm[i], rn[j], acc[i][j]);
        }
        if (it + 1 < NT) {
            int nb = buf ^ 1;
            As[nb][cA + 0][rA] = an.x; As[nb][cA + 1][rA] = an.y;
            As[nb][cA + 2][rA] = an.z; As[nb][cA + 3][rA] = an.w;
            Bs[nb][cA + 0][rA] = bn.x; Bs[nb][cA + 1][rA] = bn.y;
            Bs[nb][cA + 2][rA] = bn.z; Bs[nb][cA + 3][rA] = bn.w;
            __syncthreads();
            buf = nb;
        }
    }

    // epilogue: add base z0 = cbz[m][k] + y[b]
#pragma unroll
    for (int i = 0; i < 8; ++i) {
        int r = cRow + tRow + i;
        int eb = r >> 8, ek = r & 255;
        const float* cbzr = g_cbz + (m * K_ + ek) * D_ + tCol;
        const float* yr   = g_y + eb * D_ + tCol;
        float* cp = g_z + r * O + tCol;
#pragma unroll
        for (int j4 = 0; j4 < 8; j4 += 4) {
            float4 v = make_float4(acc[i][j4], acc[i][j4 + 1], acc[i][j4 + 2], acc[i][j4 + 3]);
            float4 c = *(const float4*)(cbzr + j4);
            float4 y = *(const float4*)(yr + j4);
            v.x += c.x + y.x; v.y += c.y + y.y;
            v.z += c.z + y.z; v.w += c.w + y.w;
            *(float4*)(cp + j4) = v;
        }
    }
}

// ---- step 0: argmin_k |x - cb0[k]|^2; write xhat, side0, code0 ----
__global__ void k_step0(const float* __restrict__ x, const float* __restrict__ cb0,
                        float* __restrict__ out) {
    int b = blockIdx.x, t = threadIdx.x;
    int w = t >> 5, lane = t & 31;
    __shared__ float4 xs[32];
    __shared__ float  sd[256];
    __shared__ int    si[256];
    if (t < 32) xs[t] = ((const float4*)x)[b * 32 + t];
    __syncthreads();
    float4 xv = xs[lane];
    for (int i = 0; i < 32; ++i) {
        int k = w * 32 + i;
        float4 c = ((const float4*)cb0)[k * 32 + lane];
        float a1 = c.x * c.x + c.y * c.y + c.z * c.z + c.w * c.w;
        float a2 = xv.x * c.x + xv.y * c.y + xv.z * c.z + xv.w * c.w;
        warp_red2(a1, a2);
        if (lane == 0) sd[k] = a1 - 2.f * a2;
    }
    si[t] = t;
    __syncthreads();
    for (int s = 128; s; s >>= 1) {
        if (t < s) {
            float o = sd[t + s]; int oi = si[t + s];
            if (o < sd[t] || (o == sd[t] && oi < si[t])) { sd[t] = o; si[t] = oi; }
        }
        __syncthreads();
    }
    int kb = si[0];
    if (t < D_) {
        float v = cb0[kb * D_ + t];
        g_xa[b * D_ + t] = v;
        out[OUT_SIDE + b * D_ + t] = v;       // side[0]
    }
    if (t == 0) out[OUT_CODES + b * M_] = (float)kb;
}

// ---- step m: zf = z + xhat; argmin_k (|zf|^2 - 2 x.zf); update xhat; emit outputs ----
__global__ void k_argupd(const float* __restrict__ x, float* __restrict__ out,
                         int m, int ping) {
    const float* xin = ping ? g_xb : g_xa;
    float*       xout = ping ? g_xa : g_xb;
    int b = blockIdx.x, t = threadIdx.x;
    int w = t >> 5, lane = t & 31;
    __shared__ float4 xs[32], hs[32];
    __shared__ float  sd[256];
    __shared__ int    si[256];
    if (t < 32) {
        xs[t] = ((const float4*)x)[b * 32 + t];
        hs[t] = ((const float4*)xin)[b * 32 + t];
    }
    __syncthreads();
    float4 xv = xs[lane], hv = hs[lane];
    const float4* zr = (const float4*)g_z + b * (K_ * 32);
    for (int i = 0; i < 32; ++i) {
        int k = w * 32 + i;
        float4 z = zr[k * 32 + lane];
        z.x += hv.x; z.y += hv.y; z.z += hv.z; z.w += hv.w;
        float a1 = z.x * z.x + z.y * z.y + z.z * z.z + z.w * z.w;
        float a2 = xv.x * z.x + xv.y * z.y + xv.z * z.z + xv.w * z.w;
        warp_red2(a1, a2);
        if (lane == 0) sd[k] = a1 - 2.f * a2;
    }
    si[t] = t;
    __syncthreads();
    for (int s = 128; s; s >>= 1) {
        if (t < s) {
            float o = sd[t + s]; int oi = si[t + s];
            if (o < sd[t] || (o == sd[t] && oi < si[t])) { sd[t] = o; si[t] = oi; }
        }
        __syncthreads();
    }
    int kb = si[0];
    if (t < D_) {
        float v = g_z[(b * K_ + kb) * D_ + t] + xin[b * D_ + t];
        xout[b * D_ + t] = v;
        out[OUT_SIDE + (m + 1) * SIDE_SZ + b * D_ + t] = v;  // side[m+1]
        if (m == M_ - 2) out[b * D_ + t] = v;                // final xhat
    }
    if (t == 0) out[OUT_CODES + b * M_ + m + 1] = (float)kb;
}

extern "C" void kernel_launch(void* const* d_in, const int* in_sizes, int n_in,
                              void* d_out, int out_size) {
    const float* x   = (const float*)d_in[0];
    const float* cb0 = (const float*)d_in[1];
    const float* cbs = (const float*)d_in[2];
    const float* Wc  = (const float*)d_in[3];
    const float* bc  = (const float*)d_in[4];
    const float* W1  = (const float*)d_in[5];
    const float* W2  = (const float*)d_in[6];
    float* out = (float*)d_out;

    // weight-only precomputes
    k_cbz<<<(M_ - 1) * K_, D_>>>(cbs, Wc, bc);
    k_p1<<<(M_ - 1) * K_, H_>>>(W1);
    k_step0<<<BS_, 256>>>(x, cb0, out);

    int ping = 0;   // xhat currently in g_xa
    for (int m = 0; m < M_ - 1; ++m) {
        k_y<<<BS_, D_>>>(Wc, m, ping);
        k_q1<<<BS_, H_>>>(W1, m);
        // layer 0 (GEMM1 eliminated algebraically; base + h0 fused here)
        k_gemm2_l0<<<dim3(1, NR / 128), 256>>>(W2 + (m * 2) * D_ * H_, m);
        // layer 1 (full GEMMs)
        k_gemm1<<<dim3(H_ / 128, NR / 128), 256>>>(W1 + (m * 2 + 1) * H_ * D_);
        k_gemm2<<<dim3(D_ / 128, NR / 128), 256>>>(W2 + (m * 2 + 1) * D_ * H_);
        k_argupd<<<BS_, 256>>>(x, out, m, ping);
        ping ^= 1;
    }
}